// round 4
// baseline (speedup 1.0000x reference)
#include <cuda_runtime.h>
#include <cstdint>
#include <cstddef>

#define TOKENS 16384
#define HIDDEN 2048
#define NEXP   64
#define BM     128
#define BK     16
#define NTH    256
#define NIT    (HIDDEN / BK)
#define STRA   20          // A row stride in floats (LDS.128 conflict-free)
#define STRL   65          // logit-tile row stride (odd => conflict-free scalar)

#define OFF_GATES (TOKENS * 2)
#define OFF_SEL   (OFF_GATES + TOKENS * NEXP)
#define OFF_Z     (OFF_SEL + TOKENS * 2)

__device__ float g_zpart[TOKENS / BM];

__device__ __forceinline__ unsigned long long ffma2(unsigned long long a,
                                                    unsigned long long b,
                                                    unsigned long long c) {
    unsigned long long d;
    asm("fma.rn.f32x2 %0, %1, %2, %3;" : "=l"(d) : "l"(a), "l"(b), "l"(c));
    return d;
}
__device__ __forceinline__ unsigned long long packdup(float v) {
    unsigned long long d;
    asm("mov.b64 %0, {%1, %1};" : "=l"(d) : "f"(v));
    return d;
}
__device__ __forceinline__ float2 unpack2(unsigned long long v) {
    float2 f;
    asm("mov.b64 {%0, %1}, %2;" : "=f"(f.x), "=f"(f.y) : "l"(v));
    return f;
}

__device__ __forceinline__ void warp_argmax(float& v, int& i) {
#pragma unroll
    for (int m = 16; m; m >>= 1) {
        float ov = __shfl_xor_sync(0xffffffffu, v, m);
        int   oi = __shfl_xor_sync(0xffffffffu, i, m);
        if (ov > v || (ov == v && oi < i)) { v = ov; i = oi; }
    }
}
__device__ __forceinline__ float warp_sum(float s) {
#pragma unroll
    for (int m = 16; m; m >>= 1) s += __shfl_xor_sync(0xffffffffu, s, m);
    return s;
}

// ---------------------------------------------------------------------------
// Fused kernel: GEMM (fp32, f32x2 FFMA, double-buffered smem) + sparse-mixer
// routing + gates + per-CTA z partial. grid = 128 CTAs, 256 threads.
// GEMM: thread t -> token t&127, experts [(t>>7)*32, +32), 32 fp32 accs.
// ---------------------------------------------------------------------------
__global__ __launch_bounds__(NTH, 1) void fused_kernel(const float* __restrict__ x,
                                                       const float* __restrict__ w,
                                                       float* __restrict__ out) {
    // union: GEMM tiles (As 2*128*20 + Bs 2*16*64 = 7168 floats)
    //        vs logit tile Ls (128*65 = 8320 floats)
    __shared__ __align__(16) float SM[8320];
    __shared__ float zred[NTH / 32];

    float* As = SM;                 // [2][128][STRA]
    float* Bs = SM + 2 * BM * STRA; // [2][BK][NEXP]

    const int t   = threadIdx.x;
    const int m0  = blockIdx.x * BM;
    const int tok = t & (BM - 1);
    const int e0  = (t >> 7) << 5;  // 0 or 32 (warp-uniform)

    const int a_kq  = t & 3;        // float4 col within BK
    const int a_row = t >> 2;       // rows a_row and a_row+64
    const int b_er  = t & 63;       // expert row of w
    const int b_kq  = t >> 6;       // float4 col within BK

    const float* xg = x + (size_t)(m0 + a_row) * HIDDEN + a_kq * 4;
    const float* wg = w + (size_t)b_er * HIDDEN + b_kq * 4;

    float4 pa0, pa1, pb;
    unsigned long long acc[16];
#pragma unroll
    for (int i = 0; i < 16; i++) acc[i] = 0ULL;

    // initial tile -> buf 0
    pa0 = *(const float4*)(xg);
    pa1 = *(const float4*)(xg + (size_t)64 * HIDDEN);
    pb  = *(const float4*)(wg);
    *(float4*)&As[a_row * STRA + a_kq * 4]        = pa0;   // 80B row stride: 16B-aligned
    *(float4*)&As[(a_row + 64) * STRA + a_kq * 4] = pa1;
    Bs[(b_kq * 4 + 0) * NEXP + b_er] = pb.x;
    Bs[(b_kq * 4 + 1) * NEXP + b_er] = pb.y;
    Bs[(b_kq * 4 + 2) * NEXP + b_er] = pb.z;
    Bs[(b_kq * 4 + 3) * NEXP + b_er] = pb.w;
    __syncthreads();

    int buf = 0;
    for (int it = 0; it < NIT; it++) {
        if (it + 1 < NIT) {
            const int kc = (it + 1) * BK;
            pa0 = *(const float4*)(xg + kc);
            pa1 = *(const float4*)(xg + (size_t)64 * HIDDEN + kc);
            pb  = *(const float4*)(wg + kc);
        }
        const float* Ab = As + buf * (BM * STRA) + tok * STRA;
        const float* Bb = Bs + buf * (BK * NEXP) + e0;
#pragma unroll
        for (int k4 = 0; k4 < BK / 4; k4++) {
            // conflict-free LDS.128: 4 consecutive k-values of this token
            const float4 av = *(const float4*)(Ab + k4 * 4);
            const float a4[4] = {av.x, av.y, av.z, av.w};
#pragma unroll
            for (int j = 0; j < 4; j++) {
                const unsigned long long a2 = packdup(a4[j]);
                const ulonglong2* bp = (const ulonglong2*)(Bb + (k4 * 4 + j) * NEXP);
#pragma unroll
                for (int q = 0; q < 8; q++) {   // 8 broadcast LDS.128 = 32 experts
                    const ulonglong2 b = bp[q];
                    acc[2 * q]     = ffma2(a2, b.x, acc[2 * q]);
                    acc[2 * q + 1] = ffma2(a2, b.y, acc[2 * q + 1]);
                }
            }
        }
        if (it + 1 < NIT) {
            __syncthreads();
            const int nb = buf ^ 1;
            float* Asn = As + nb * (BM * STRA);
            float* Bsn = Bs + nb * (BK * NEXP);
            *(float4*)&Asn[a_row * STRA + a_kq * 4]        = pa0;
            *(float4*)&Asn[(a_row + 64) * STRA + a_kq * 4] = pa1;
            Bsn[(b_kq * 4 + 0) * NEXP + b_er] = pb.x;
            Bsn[(b_kq * 4 + 1) * NEXP + b_er] = pb.y;
            Bsn[(b_kq * 4 + 2) * NEXP + b_er] = pb.z;
            Bsn[(b_kq * 4 + 3) * NEXP + b_er] = pb.w;
            __syncthreads();
            buf = nb;
        }
    }

    // -------- publish logits to smem (aliases As/Bs) --------
    __syncthreads();                 // everyone done reading tiles
    float* Ls = SM;                  // [BM][STRL]
    {
        float* dst = Ls + tok * STRL + e0;
#pragma unroll
        for (int q = 0; q < 8; q++) {
            const float2 lo = unpack2(acc[2 * q]);
            const float2 hi = unpack2(acc[2 * q + 1]);
            dst[4 * q + 0] = lo.x;   // stride-65 rows: scalar STS conflict-free
            dst[4 * q + 1] = lo.y;
            dst[4 * q + 2] = hi.x;
            dst[4 * q + 3] = hi.y;
        }
    }
    __syncthreads();

    // -------- routing: warp per token, 16 tokens per warp --------
    const int wid  = t >> 5;
    const int lane = t & 31;
    const float NINF = __int_as_float(0xff800000);
    float zacc = 0.f;

    for (int s = 0; s < BM / (NTH / 32); s++) {
        const int tk = wid * (BM / (NTH / 32)) + s;
        const float* row = Ls + tk * STRL;
        const float v0 = row[lane];
        const float v1 = row[lane + 32];
        const int   i0 = lane, i1 = lane + 32;

        // ---- pass 1: top-1 ----
        float bv; int bi;
        if (v0 >= v1) { bv = v0; bi = i0; } else { bv = v1; bi = i1; }
        warp_argmax(bv, bi);
        const float mx1 = bv;
        const int   s1  = bi;

        const float ea0  = expf(v0 - mx1);
        const float ea1  = expf(v1 - mx1);
        const float sAll = warp_sum(ea0 + ea1);

        // mask: (mx - scores)/max(|scores|, mx) > 2*jitter_eps
        const float f0 = fmaxf(fabsf(v0), mx1);
        const float f1 = fmaxf(fabsf(v1), mx1);
        const bool mask10 = ((mx1 - v0) / f0) > 0.02f;
        const bool mask11 = ((mx1 - v1) / f1) > 0.02f;
        const float sum1  = warp_sum((mask10 ? 0.f : ea0) + (mask11 ? 0.f : ea1));
        const float mult1 = 1.0f / sum1;

        // ---- pass 2: mask out s1 ----
        const float w0 = (i0 == s1) ? NINF : v0;
        const float w1 = (i1 == s1) ? NINF : v1;
        float bv2; int bi2;
        if (w0 >= w1) { bv2 = w0; bi2 = i0; } else { bv2 = w1; bi2 = i1; }
        warp_argmax(bv2, bi2);
        const float mx2 = bv2;
        const int   s2  = bi2;

        const float g0 = fmaxf(fabsf(v0), mx2);
        const float g1 = fmaxf(fabsf(v1), mx2);
        const bool mask20 = ((mx2 - v0) / g0) > 0.02f;
        const bool mask21 = ((mx2 - v1) / g1) > 0.02f;
        const float e20 = (i0 == s1 || mask20) ? 0.f : expf(v0 - mx2);
        const float e21 = (i1 == s1 || mask21) ? 0.f : expf(v1 - mx2);
        const float sum2  = warp_sum(e20 + e21);
        const float mult2 = 1.0f / sum2;

        // ---- outputs ----
        const int gtok = m0 + tk;
        const float invAll = 1.0f / sAll;
        out[OFF_GATES + (size_t)gtok * NEXP + lane]      = ea0 * invAll;
        out[OFF_GATES + (size_t)gtok * NEXP + lane + 32] = ea1 * invAll;
        if (lane == 0) {
            out[gtok * 2 + 0] = mult1;
            out[gtok * 2 + 1] = mult2;
            out[OFF_SEL + gtok * 2 + 0] = (float)s1;
            out[OFF_SEL + gtok * 2 + 1] = (float)s2;
            const float lse = mx1 + logf(sAll);
            zacc += lse * lse;
        }
    }

    if (lane == 0) zred[wid] = zacc;
    __syncthreads();
    if (t == 0) {
        float s = 0.f;
#pragma unroll
        for (int i = 0; i < NTH / 32; i++) s += zred[i];
        g_zpart[blockIdx.x] = s;
    }
}

// ---------------------------------------------------------------------------
// Final deterministic z-loss reduction over 128 CTA partials
// ---------------------------------------------------------------------------
__global__ void zfin_kernel(float* __restrict__ out) {
    __shared__ float r[TOKENS / BM];
    const int t = threadIdx.x;
    r[t] = g_zpart[t];
    __syncthreads();
    for (int stride = (TOKENS / BM) / 2; stride > 0; stride >>= 1) {
        if (t < stride) r[t] += r[t + stride];
        __syncthreads();
    }
    if (t == 0) out[OFF_Z] = 0.001f * (r[0] / (float)TOKENS);
}

extern "C" void kernel_launch(void* const* d_in, const int* in_sizes, int n_in,
                              void* d_out, int out_size) {
    const float* x = (const float*)d_in[0];
    const float* w = (const float*)d_in[1];
    float* out = (float*)d_out;

    fused_kernel<<<TOKENS / BM, NTH>>>(x, w, out);
    zfin_kernel<<<1, TOKENS / BM>>>(out);
}

// round 11
// speedup vs baseline: 1.4914x; 1.4914x over previous
#include <cuda_runtime.h>
#include <cuda_bf16.h>
#include <cstdint>
#include <cstddef>

#define TOKENS 16384
#define HIDDEN 2048
#define NEXP   64
#define BM     128
#define BK     64
#define NIT    (HIDDEN / BK)   // 32
#define NTH    256

#define OFF_GATES (TOKENS * 2)
#define OFF_SEL   (OFF_GATES + TOKENS * NEXP)
#define OFF_Z     (OFF_SEL + TOKENS * 2)

// ---- smem layout (bytes, dynamic) ----
#define ASTRB 144
#define ALVL  (BM * ASTRB)          // 18432
#define ABUF  (3 * ALVL)            // 55296
#define BLVL  (NEXP * ASTRB)        // 9216
#define BBUF  (3 * BLVL)            // 27648
#define TILEB (ABUF + BBUF)         // 82944
#define SM_ZRED  0
#define SM_TILES 1024
#define SMEM_TOTAL (SM_TILES + 2 * TILEB)   // 166912
#define STRL 65

__device__ unsigned int g_wsplit[3 * 64 * 1024];
__device__ float g_zpart[TOKENS / BM];

// ---------------- helpers ----------------
__device__ __forceinline__ uint32_t smem_u32(const void* p) {
    uint32_t a;
    asm("{ .reg .u64 t; cvta.to.shared.u64 t, %1; cvt.u32.u64 %0, t; }" : "=r"(a) : "l"(p));
    return a;
}
__device__ __forceinline__ void ldsm4(uint32_t* r, uint32_t addr) {
    asm volatile("ldmatrix.sync.aligned.m8n8.x4.shared.b16 {%0,%1,%2,%3}, [%4];"
                 : "=r"(r[0]), "=r"(r[1]), "=r"(r[2]), "=r"(r[3]) : "r"(addr));
}
__device__ __forceinline__ void mma16816(float* d, const uint32_t* a, const uint32_t* b) {
    asm volatile("mma.sync.aligned.m16n8k16.row.col.f32.bf16.bf16.f32 "
                 "{%0,%1,%2,%3}, {%4,%5,%6,%7}, {%8,%9}, {%0,%1,%2,%3};"
                 : "+f"(d[0]), "+f"(d[1]), "+f"(d[2]), "+f"(d[3])
                 : "r"(a[0]), "r"(a[1]), "r"(a[2]), "r"(a[3]), "r"(b[0]), "r"(b[1]));
}
__device__ __forceinline__ void sts64(uint32_t a, uint32_t lo, uint32_t hi) {
    asm volatile("st.shared.v2.b32 [%0], {%1, %2};" :: "r"(a), "r"(lo), "r"(hi) : "memory");
}
__device__ __forceinline__ void sts128(uint32_t a, uint4 v) {
    asm volatile("st.shared.v4.b32 [%0], {%1, %2, %3, %4};"
                 :: "r"(a), "r"(v.x), "r"(v.y), "r"(v.z), "r"(v.w) : "memory");
}
// 3-way bf16 split of two floats (lo=x0, hi=x1); residuals exact (Sterbenz).
__device__ __forceinline__ void split2(float x0, float x1,
                                       uint32_t& p0, uint32_t& p1, uint32_t& p2) {
    asm("cvt.rn.satfinite.bf16x2.f32 %0, %1, %2;" : "=r"(p0) : "f"(x1), "f"(x0));
    float f0lo = __uint_as_float(p0 << 16);
    float f0hi = __uint_as_float(p0 & 0xffff0000u);
    float r0 = x0 - f0lo, r1 = x1 - f0hi;
    asm("cvt.rn.satfinite.bf16x2.f32 %0, %1, %2;" : "=r"(p1) : "f"(r1), "f"(r0));
    float f1lo = __uint_as_float(p1 << 16);
    float f1hi = __uint_as_float(p1 & 0xffff0000u);
    float s0 = r0 - f1lo, s1 = r1 - f1hi;
    asm("cvt.rn.satfinite.bf16x2.f32 %0, %1, %2;" : "=r"(p2) : "f"(s1), "f"(s0));
}
__device__ __forceinline__ void warp_argmax(float& v, int& i) {
#pragma unroll
    for (int m = 16; m; m >>= 1) {
        float ov = __shfl_xor_sync(0xffffffffu, v, m);
        int   oi = __shfl_xor_sync(0xffffffffu, i, m);
        if (ov > v || (ov == v && oi < i)) { v = ov; i = oi; }
    }
}
__device__ __forceinline__ float warp_sum(float s) {
#pragma unroll
    for (int m = 16; m; m >>= 1) s += __shfl_xor_sync(0xffffffffu, s, m);
    return s;
}

// ---------------------------------------------------------------------------
// Pre-kernel: split w into 3 bf16 levels
// ---------------------------------------------------------------------------
__global__ void wsplit_kernel(const float* __restrict__ w) {
    const int p4 = blockIdx.x * blockDim.x + threadIdx.x;
    const float4 v0 = *(const float4*)(w + (size_t)p4 * 8);
    const float4 v1 = *(const float4*)(w + (size_t)p4 * 8 + 4);
    const float xs[8] = {v0.x, v0.y, v0.z, v0.w, v1.x, v1.y, v1.z, v1.w};
#pragma unroll
    for (int j = 0; j < 4; j++) {
        uint32_t a, b, c;
        split2(xs[2 * j], xs[2 * j + 1], a, b, c);
        g_wsplit[0 * 65536 + p4 * 4 + j] = a;
        g_wsplit[1 * 65536 + p4 * 4 + j] = b;
        g_wsplit[2 * 65536 + p4 * 4 + j] = c;
    }
}

// ---------------------------------------------------------------------------
// Fused kernel: bf16x6 emulated-fp32 GEMM via mma.sync, chunked RN accumulation.
// grid = 128 CTAs, 256 threads (8 warps); warp owns rows [wid*16, +16) x 64 experts.
// ---------------------------------------------------------------------------
__global__ __launch_bounds__(NTH, 1) void fused_kernel(const float* __restrict__ x,
                                                       float* __restrict__ out) {
    extern __shared__ __align__(1024) char smem[];
    const uint32_t sb = smem_u32(smem);
    const int t    = threadIdx.x;
    const int wid  = t >> 5;
    const int lane = t & 31;
    const int m0   = blockIdx.x * BM;

    const int xrow = t >> 1;
    const int xcb  = (t & 1) * 32;
    const float* xg = x + (size_t)(m0 + xrow) * HIDDEN + xcb;

    const uint32_t a_off = (uint32_t)((wid * 16 + (lane & 15)) * ASTRB + (lane >> 4) * 16);
    const uint32_t b_off = (uint32_t)(((lane >> 4) * 8 + (lane & 7)) * ASTRB + ((lane >> 3) & 1) * 16);

    float run[8][4];     // RN fp32 running sums (final logits)
#pragma unroll
    for (int j = 0; j < 8; j++)
#pragma unroll
        for (int c = 0; c < 4; c++) run[j][c] = 0.f;

    float4 xa[8];
    uint4  wa[6];

    // prefetch iter 0
#pragma unroll
    for (int j = 0; j < 8; j++) xa[j] = *(const float4*)(xg + 4 * j);
#pragma unroll
    for (int i = 0; i < 6; i++) {
        const int idx = i * 256 + t;
        const int lvl = idx >> 9, r = idx & 511, row = r >> 3, c16 = r & 7;
        wa[i] = *(const uint4*)(g_wsplit + lvl * 65536 + row * 1024 + c16 * 4);
    }

    // term order: SMALL -> LARGE so in-TC RZ events happen at small magnitude
    const int TA[6] = {2, 1, 0, 1, 0, 0};
    const int TB[6] = {0, 1, 2, 0, 1, 0};

    for (int it = 0; it < NIT; it++) {
        const uint32_t tb = sb + SM_TILES + (it & 1) * TILEB;
        const uint32_t abase = tb;
        const uint32_t bbase = tb + ABUF;

        // ---- fill: convert+store x (3 levels), store pre-split w ----
#pragma unroll
        for (int j = 0; j < 8; j++) {
            uint32_t a0, a1, a2, b0, b1, b2;
            split2(xa[j].x, xa[j].y, a0, a1, a2);
            split2(xa[j].z, xa[j].w, b0, b1, b2);
            const uint32_t off = (uint32_t)(xrow * ASTRB + (xcb + 4 * j) * 2);
            sts64(abase + 0 * ALVL + off, a0, b0);
            sts64(abase + 1 * ALVL + off, a1, b1);
            sts64(abase + 2 * ALVL + off, a2, b2);
        }
#pragma unroll
        for (int i = 0; i < 6; i++) {
            const int idx = i * 256 + t;
            const int lvl = idx >> 9, r = idx & 511, row = r >> 3, c16 = r & 7;
            sts128(bbase + lvl * BLVL + (uint32_t)(row * ASTRB + c16 * 16), wa[i]);
        }
        __syncthreads();

        // ---- prefetch next iter ----
        if (it + 1 < NIT) {
            const int kc = (it + 1) * BK;
#pragma unroll
            for (int j = 0; j < 8; j++) xa[j] = *(const float4*)(xg + kc + 4 * j);
#pragma unroll
            for (int i = 0; i < 6; i++) {
                const int idx = i * 256 + t;
                const int lvl = idx >> 9, r = idx & 511, row = r >> 3, c16 = r & 7;
                wa[i] = *(const uint4*)(g_wsplit + lvl * 65536 + row * 1024 + (kc >> 1) + c16 * 4);
            }
        }

        // ---- per-chunk mma accumulator (reset to 0 each iteration) ----
        float acc[8][4];
#pragma unroll
        for (int j = 0; j < 8; j++)
#pragma unroll
            for (int c = 0; c < 4; c++) acc[j][c] = 0.f;

#pragma unroll
        for (int s = 0; s < 6; s++) {
            const uint32_t ab = abase + TA[s] * ALVL + a_off;
            const uint32_t bb = bbase + TB[s] * BLVL + b_off;
#pragma unroll
            for (int kk = 0; kk < 4; kk++) {
                uint32_t af[4];
                ldsm4(af, ab + kk * 32);
                uint32_t bf[4][4];
#pragma unroll
                for (int g = 0; g < 4; g++) ldsm4(bf[g], bb + g * (16 * ASTRB) + kk * 32);
#pragma unroll
                for (int g = 0; g < 4; g++) {
                    mma16816(acc[2 * g],     af, &bf[g][0]);
                    mma16816(acc[2 * g + 1], af, &bf[g][2]);
                }
            }
        }
        // fold chunk into RN fp32 running sum (breaks the in-TC RZ chain)
#pragma unroll
        for (int j = 0; j < 8; j++)
#pragma unroll
            for (int c = 0; c < 4; c++) run[j][c] += acc[j][c];

        __syncthreads();
    }

    // ---- publish logits to smem tile Ls[128][65] ----
    float* Ls = (float*)(smem + SM_TILES);
    {
        const int r0 = wid * 16 + (lane >> 2);
        const int c0 = (lane & 3) * 2;
#pragma unroll
        for (int j = 0; j < 8; j++) {
            Ls[r0 * STRL + j * 8 + c0]           = run[j][0];
            Ls[r0 * STRL + j * 8 + c0 + 1]       = run[j][1];
            Ls[(r0 + 8) * STRL + j * 8 + c0]     = run[j][2];
            Ls[(r0 + 8) * STRL + j * 8 + c0 + 1] = run[j][3];
        }
    }
    __syncthreads();

    // ---- routing: warp per token, 16 tokens per warp ----
    const float NINF = __int_as_float(0xff800000);
    float zacc = 0.f;

    for (int st = 0; st < 16; st++) {
        const int tk = wid * 16 + st;
        const float* row = Ls + tk * STRL;
        const float v0 = row[lane];
        const float v1 = row[lane + 32];
        const int   i0 = lane, i1 = lane + 32;

        // pass 1
        float bv; int bi;
        if (v0 >= v1) { bv = v0; bi = i0; } else { bv = v1; bi = i1; }
        warp_argmax(bv, bi);
        const float mx1 = bv;
        const int   s1  = bi;

        const float ea0  = expf(v0 - mx1);
        const float ea1  = expf(v1 - mx1);
        const float sAll = warp_sum(ea0 + ea1);

        const float f0 = fmaxf(fabsf(v0), mx1);
        const float f1 = fmaxf(fabsf(v1), mx1);
        const bool mask10 = ((mx1 - v0) / f0) > 0.02f;
        const bool mask11 = ((mx1 - v1) / f1) > 0.02f;
        const float sum1  = warp_sum((mask10 ? 0.f : ea0) + (mask11 ? 0.f : ea1));
        const float mult1 = 1.0f / sum1;

        // pass 2
        const float w0 = (i0 == s1) ? NINF : v0;
        const float w1 = (i1 == s1) ? NINF : v1;
        float bv2; int bi2;
        if (w0 >= w1) { bv2 = w0; bi2 = i0; } else { bv2 = w1; bi2 = i1; }
        warp_argmax(bv2, bi2);
        const float mx2 = bv2;
        const int   s2  = bi2;

        const float g0 = fmaxf(fabsf(v0), mx2);
        const float g1 = fmaxf(fabsf(v1), mx2);
        const bool mask20 = ((mx2 - v0) / g0) > 0.02f;
        const bool mask21 = ((mx2 - v1) / g1) > 0.02f;
        const float e20 = (i0 == s1 || mask20) ? 0.f : expf(v0 - mx2);
        const float e21 = (i1 == s1 || mask21) ? 0.f : expf(v1 - mx2);
        const float sum2  = warp_sum(e20 + e21);
        const float mult2 = 1.0f / sum2;

        // outputs
        const int gtok = m0 + tk;
        const float invAll = 1.0f / sAll;
        out[OFF_GATES + (size_t)gtok * NEXP + lane]      = ea0 * invAll;
        out[OFF_GATES + (size_t)gtok * NEXP + lane + 32] = ea1 * invAll;
        if (lane == 0) {
            out[gtok * 2 + 0] = mult1;
            out[gtok * 2 + 1] = mult2;
            out[OFF_SEL + gtok * 2 + 0] = (float)s1;
            out[OFF_SEL + gtok * 2 + 1] = (float)s2;
            const float lse = mx1 + logf(sAll);
            zacc += lse * lse;
        }
    }

    float* zred = (float*)(smem + SM_ZRED);
    if (lane == 0) zred[wid] = zacc;
    __syncthreads();
    if (t == 0) {
        float s = 0.f;
#pragma unroll
        for (int i = 0; i < 8; i++) s += zred[i];
        g_zpart[blockIdx.x] = s;
    }
}

// ---------------------------------------------------------------------------
// Final deterministic z-loss reduction
// ---------------------------------------------------------------------------
__global__ void zfin_kernel(float* __restrict__ out) {
    __shared__ float r[TOKENS / BM];
    const int t = threadIdx.x;
    r[t] = g_zpart[t];
    __syncthreads();
    for (int stride = (TOKENS / BM) / 2; stride > 0; stride >>= 1) {
        if (t < stride) r[t] += r[t + stride];
        __syncthreads();
    }
    if (t == 0) out[OFF_Z] = 0.001f * (r[0] / (float)TOKENS);
}

extern "C" void kernel_launch(void* const* d_in, const int* in_sizes, int n_in,
                              void* d_out, int out_size) {
    const float* x = (const float*)d_in[0];
    const float* w = (const float*)d_in[1];
    float* out = (float*)d_out;

    cudaFuncSetAttribute(fused_kernel, cudaFuncAttributeMaxDynamicSharedMemorySize, SMEM_TOTAL);

    wsplit_kernel<<<64, 256>>>(w);
    fused_kernel<<<TOKENS / BM, NTH, SMEM_TOTAL>>>(x, out);
    zfin_kernel<<<1, TOKENS / BM>>>(out);
}

// round 12
// speedup vs baseline: 2.1648x; 1.4514x over previous
#include <cuda_runtime.h>
#include <cuda_bf16.h>
#include <cstdint>
#include <cstddef>

#define TOKENS 16384
#define HIDDEN 2048
#define NEXP   64
#define BM     128
#define BK     64
#define NIT    (HIDDEN / BK)   // 32
#define NTH    512

#define OFF_GATES (TOKENS * 2)
#define OFF_SEL   (OFF_GATES + TOKENS * NEXP)
#define OFF_Z     (OFF_SEL + TOKENS * 2)

// ---- smem layout (bytes, dynamic) ----
#define ASTRB 144
#define ALVL  (BM * ASTRB)          // 18432
#define ABUF  (3 * ALVL)            // 55296
#define BLVL  (NEXP * ASTRB)        // 9216
#define BBUF  (3 * BLVL)            // 27648
#define TILEB (ABUF + BBUF)         // 82944
#define SM_ZRED  0
#define SM_TILES 1024
#define SMEM_TOTAL (SM_TILES + 2 * TILEB)   // 166912
#define STRL 65

__device__ unsigned int g_wsplit[3 * 64 * 1024];
__device__ float g_zpart[TOKENS / BM];

// ---------------- helpers ----------------
__device__ __forceinline__ uint32_t smem_u32(const void* p) {
    uint32_t a;
    asm("{ .reg .u64 t; cvta.to.shared.u64 t, %1; cvt.u32.u64 %0, t; }" : "=r"(a) : "l"(p));
    return a;
}
__device__ __forceinline__ void ldsm4(uint32_t* r, uint32_t addr) {
    asm volatile("ldmatrix.sync.aligned.m8n8.x4.shared.b16 {%0,%1,%2,%3}, [%4];"
                 : "=r"(r[0]), "=r"(r[1]), "=r"(r[2]), "=r"(r[3]) : "r"(addr));
}
__device__ __forceinline__ void mma16816(float* d, const uint32_t* a, const uint32_t* b) {
    asm volatile("mma.sync.aligned.m16n8k16.row.col.f32.bf16.bf16.f32 "
                 "{%0,%1,%2,%3}, {%4,%5,%6,%7}, {%8,%9}, {%0,%1,%2,%3};"
                 : "+f"(d[0]), "+f"(d[1]), "+f"(d[2]), "+f"(d[3])
                 : "r"(a[0]), "r"(a[1]), "r"(a[2]), "r"(a[3]), "r"(b[0]), "r"(b[1]));
}
__device__ __forceinline__ void sts64(uint32_t a, uint32_t lo, uint32_t hi) {
    asm volatile("st.shared.v2.b32 [%0], {%1, %2};" :: "r"(a), "r"(lo), "r"(hi) : "memory");
}
__device__ __forceinline__ void sts128(uint32_t a, uint4 v) {
    asm volatile("st.shared.v4.b32 [%0], {%1, %2, %3, %4};"
                 :: "r"(a), "r"(v.x), "r"(v.y), "r"(v.z), "r"(v.w) : "memory");
}
// 3-way bf16 split of two floats (lo=x0, hi=x1); residuals exact (Sterbenz).
__device__ __forceinline__ void split2(float x0, float x1,
                                       uint32_t& p0, uint32_t& p1, uint32_t& p2) {
    asm("cvt.rn.satfinite.bf16x2.f32 %0, %1, %2;" : "=r"(p0) : "f"(x1), "f"(x0));
    float f0lo = __uint_as_float(p0 << 16);
    float f0hi = __uint_as_float(p0 & 0xffff0000u);
    float r0 = x0 - f0lo, r1 = x1 - f0hi;
    asm("cvt.rn.satfinite.bf16x2.f32 %0, %1, %2;" : "=r"(p1) : "f"(r1), "f"(r0));
    float f1lo = __uint_as_float(p1 << 16);
    float f1hi = __uint_as_float(p1 & 0xffff0000u);
    float s0 = r0 - f1lo, s1 = r1 - f1hi;
    asm("cvt.rn.satfinite.bf16x2.f32 %0, %1, %2;" : "=r"(p2) : "f"(s1), "f"(s0));
}
__device__ __forceinline__ void warp_argmax(float& v, int& i) {
#pragma unroll
    for (int m = 16; m; m >>= 1) {
        float ov = __shfl_xor_sync(0xffffffffu, v, m);
        int   oi = __shfl_xor_sync(0xffffffffu, i, m);
        if (ov > v || (ov == v && oi < i)) { v = ov; i = oi; }
    }
}
__device__ __forceinline__ float warp_sum(float s) {
#pragma unroll
    for (int m = 16; m; m >>= 1) s += __shfl_xor_sync(0xffffffffu, s, m);
    return s;
}

// ---------------------------------------------------------------------------
// Pre-kernel: split w into 3 bf16 levels
// ---------------------------------------------------------------------------
__global__ void wsplit_kernel(const float* __restrict__ w) {
    const int p4 = blockIdx.x * blockDim.x + threadIdx.x;
    const float4 v0 = *(const float4*)(w + (size_t)p4 * 8);
    const float4 v1 = *(const float4*)(w + (size_t)p4 * 8 + 4);
    const float xs[8] = {v0.x, v0.y, v0.z, v0.w, v1.x, v1.y, v1.z, v1.w};
#pragma unroll
    for (int j = 0; j < 4; j++) {
        uint32_t a, b, c;
        split2(xs[2 * j], xs[2 * j + 1], a, b, c);
        g_wsplit[0 * 65536 + p4 * 4 + j] = a;
        g_wsplit[1 * 65536 + p4 * 4 + j] = b;
        g_wsplit[2 * 65536 + p4 * 4 + j] = c;
    }
}

// ---------------------------------------------------------------------------
// Fused kernel: bf16x6 emulated-fp32 GEMM via mma.sync, chunked RN accumulation.
// grid = 128 CTAs, 512 threads (16 warps).
// Warp w: rows [(w>>1)*16, +16) x experts [(w&1)*32, +32).
// ---------------------------------------------------------------------------
__global__ __launch_bounds__(NTH, 1) void fused_kernel(const float* __restrict__ x,
                                                       float* __restrict__ out) {
    extern __shared__ __align__(1024) char smem[];
    const uint32_t sb = smem_u32(smem);
    const int t    = threadIdx.x;
    const int wid  = t >> 5;
    const int lane = t & 31;
    const int m0   = blockIdx.x * BM;

    // fill roles: thread -> x row t>>2, 16-col chunk (t&3)*16
    const int xrow = t >> 2;
    const int xcb  = (t & 3) * 16;
    const float* xg = x + (size_t)(m0 + xrow) * HIDDEN + xcb;

    // mma tile bases
    const int m_base = (wid >> 1) * 16;
    const int n_base = (wid & 1) * 32;
    const uint32_t a_off = (uint32_t)((m_base + (lane & 15)) * ASTRB + (lane >> 4) * 16);
    const uint32_t b_off = (uint32_t)((n_base + (lane >> 4) * 8 + (lane & 7)) * ASTRB +
                                      ((lane >> 3) & 1) * 16);

    float run[4][4];
#pragma unroll
    for (int j = 0; j < 4; j++)
#pragma unroll
        for (int c = 0; c < 4; c++) run[j][c] = 0.f;

    float4 xa[4];
    uint4  wa[3];

    // prefetch iter 0
#pragma unroll
    for (int j = 0; j < 4; j++) xa[j] = *(const float4*)(xg + 4 * j);
#pragma unroll
    for (int i = 0; i < 3; i++) {
        const int idx = i * 512 + t;
        const int lvl = idx >> 9, r = idx & 511, row = r >> 3, c16 = r & 7;
        wa[i] = *(const uint4*)(g_wsplit + lvl * 65536 + row * 1024 + c16 * 4);
    }

    for (int it = 0; it < NIT; it++) {
        const uint32_t tb = sb + SM_TILES + (it & 1) * TILEB;
        const uint32_t abase = tb;
        const uint32_t bbase = tb + ABUF;

        // ---- fill: convert+store x (3 levels), store pre-split w ----
#pragma unroll
        for (int j = 0; j < 4; j++) {
            uint32_t a0, a1, a2, b0, b1, b2;
            split2(xa[j].x, xa[j].y, a0, a1, a2);
            split2(xa[j].z, xa[j].w, b0, b1, b2);
            const uint32_t off = (uint32_t)(xrow * ASTRB + (xcb + 4 * j) * 2);
            sts64(abase + 0 * ALVL + off, a0, b0);
            sts64(abase + 1 * ALVL + off, a1, b1);
            sts64(abase + 2 * ALVL + off, a2, b2);
        }
#pragma unroll
        for (int i = 0; i < 3; i++) {
            const int idx = i * 512 + t;
            const int lvl = idx >> 9, r = idx & 511, row = r >> 3, c16 = r & 7;
            sts128(bbase + lvl * BLVL + (uint32_t)(row * ASTRB + c16 * 16), wa[i]);
        }
        __syncthreads();

        // ---- prefetch next iter (overlaps mma) ----
        if (it + 1 < NIT) {
            const int kc = (it + 1) * BK;
#pragma unroll
            for (int j = 0; j < 4; j++) xa[j] = *(const float4*)(xg + kc + 4 * j);
#pragma unroll
            for (int i = 0; i < 3; i++) {
                const int idx = i * 512 + t;
                const int lvl = idx >> 9, r = idx & 511, row = r >> 3, c16 = r & 7;
                wa[i] = *(const uint4*)(g_wsplit + lvl * 65536 + row * 1024 + (kc >> 1) + c16 * 4);
            }
        }

        // ---- per-chunk mma accumulator (reset each iteration) ----
        float acc[4][4];
#pragma unroll
        for (int j = 0; j < 4; j++)
#pragma unroll
            for (int c = 0; c < 4; c++) acc[j][c] = 0.f;

        // kk-outer: hoist A levels (3 ldsm), stream B levels (2 ldsm each),
        // group terms by B level; b0*c0 (largest) accumulated last.
#pragma unroll
        for (int kk = 0; kk < 4; kk++) {
            uint32_t af[3][4];
#pragma unroll
            for (int lvl = 0; lvl < 3; lvl++)
                ldsm4(af[lvl], abase + lvl * ALVL + a_off + kk * 32);

            uint32_t bf[2][4];
            // B level 2: term A0*B2
#pragma unroll
            for (int h = 0; h < 2; h++) {
                ldsm4(bf[h], bbase + 2 * BLVL + b_off + h * (16 * ASTRB) + kk * 32);
                mma16816(acc[2 * h],     af[0], &bf[h][0]);
                mma16816(acc[2 * h + 1], af[0], &bf[h][2]);
            }
            // B level 1: terms A1*B1, A0*B1
#pragma unroll
            for (int h = 0; h < 2; h++) {
                ldsm4(bf[h], bbase + 1 * BLVL + b_off + h * (16 * ASTRB) + kk * 32);
                mma16816(acc[2 * h],     af[1], &bf[h][0]);
                mma16816(acc[2 * h + 1], af[1], &bf[h][2]);
                mma16816(acc[2 * h],     af[0], &bf[h][0]);
                mma16816(acc[2 * h + 1], af[0], &bf[h][2]);
            }
            // B level 0: terms A2*B0, A1*B0, A0*B0 (largest last)
#pragma unroll
            for (int h = 0; h < 2; h++) {
                ldsm4(bf[h], bbase + 0 * BLVL + b_off + h * (16 * ASTRB) + kk * 32);
                mma16816(acc[2 * h],     af[2], &bf[h][0]);
                mma16816(acc[2 * h + 1], af[2], &bf[h][2]);
                mma16816(acc[2 * h],     af[1], &bf[h][0]);
                mma16816(acc[2 * h + 1], af[1], &bf[h][2]);
                mma16816(acc[2 * h],     af[0], &bf[h][0]);
                mma16816(acc[2 * h + 1], af[0], &bf[h][2]);
            }
        }
        // fold chunk into RN fp32 running sum (breaks in-TC RZ chain)
#pragma unroll
        for (int j = 0; j < 4; j++)
#pragma unroll
            for (int c = 0; c < 4; c++) run[j][c] += acc[j][c];

        __syncthreads();
    }

    // ---- publish logits to smem tile Ls[128][65] ----
    float* Ls = (float*)(smem + SM_TILES);
    {
        const int r0 = m_base + (lane >> 2);
        const int c0 = n_base + (lane & 3) * 2;
#pragma unroll
        for (int j = 0; j < 4; j++) {
            Ls[r0 * STRL + c0 + j * 8]           = run[j][0];
            Ls[r0 * STRL + c0 + j * 8 + 1]       = run[j][1];
            Ls[(r0 + 8) * STRL + c0 + j * 8]     = run[j][2];
            Ls[(r0 + 8) * STRL + c0 + j * 8 + 1] = run[j][3];
        }
    }
    __syncthreads();

    // ---- routing: warp per token, 8 tokens per warp ----
    const float NINF = __int_as_float(0xff800000);
    float zacc = 0.f;

    for (int st = 0; st < 8; st++) {
        const int tk = wid * 8 + st;
        const float* row = Ls + tk * STRL;
        const float v0 = row[lane];
        const float v1 = row[lane + 32];
        const int   i0 = lane, i1 = lane + 32;

        // pass 1
        float bv; int bi;
        if (v0 >= v1) { bv = v0; bi = i0; } else { bv = v1; bi = i1; }
        warp_argmax(bv, bi);
        const float mx1 = bv;
        const int   s1  = bi;

        const float ea0  = expf(v0 - mx1);
        const float ea1  = expf(v1 - mx1);
        const float sAll = warp_sum(ea0 + ea1);

        const float f0 = fmaxf(fabsf(v0), mx1);
        const float f1 = fmaxf(fabsf(v1), mx1);
        const bool mask10 = ((mx1 - v0) / f0) > 0.02f;
        const bool mask11 = ((mx1 - v1) / f1) > 0.02f;
        const float sum1  = warp_sum((mask10 ? 0.f : ea0) + (mask11 ? 0.f : ea1));
        const float mult1 = 1.0f / sum1;

        // pass 2
        const float w0 = (i0 == s1) ? NINF : v0;
        const float w1 = (i1 == s1) ? NINF : v1;
        float bv2; int bi2;
        if (w0 >= w1) { bv2 = w0; bi2 = i0; } else { bv2 = w1; bi2 = i1; }
        warp_argmax(bv2, bi2);
        const float mx2 = bv2;
        const int   s2  = bi2;

        const float g0 = fmaxf(fabsf(v0), mx2);
        const float g1 = fmaxf(fabsf(v1), mx2);
        const bool mask20 = ((mx2 - v0) / g0) > 0.02f;
        const bool mask21 = ((mx2 - v1) / g1) > 0.02f;
        const float e20 = (i0 == s1 || mask20) ? 0.f : expf(v0 - mx2);
        const float e21 = (i1 == s1 || mask21) ? 0.f : expf(v1 - mx2);
        const float sum2  = warp_sum(e20 + e21);
        const float mult2 = 1.0f / sum2;

        // outputs
        const int gtok = m0 + tk;
        const float invAll = 1.0f / sAll;
        out[OFF_GATES + (size_t)gtok * NEXP + lane]      = ea0 * invAll;
        out[OFF_GATES + (size_t)gtok * NEXP + lane + 32] = ea1 * invAll;
        if (lane == 0) {
            out[gtok * 2 + 0] = mult1;
            out[gtok * 2 + 1] = mult2;
            out[OFF_SEL + gtok * 2 + 0] = (float)s1;
            out[OFF_SEL + gtok * 2 + 1] = (float)s2;
            const float lse = mx1 + logf(sAll);
            zacc += lse * lse;
        }
    }

    float* zred = (float*)(smem + SM_ZRED);
    if (lane == 0) zred[wid] = zacc;
    __syncthreads();
    if (t == 0) {
        float s = 0.f;
#pragma unroll
        for (int i = 0; i < 16; i++) s += zred[i];
        g_zpart[blockIdx.x] = s;
    }
}

// ---------------------------------------------------------------------------
// Final deterministic z-loss reduction
// ---------------------------------------------------------------------------
__global__ void zfin_kernel(float* __restrict__ out) {
    __shared__ float r[TOKENS / BM];
    const int t = threadIdx.x;
    r[t] = g_zpart[t];
    __syncthreads();
    for (int stride = (TOKENS / BM) / 2; stride > 0; stride >>= 1) {
        if (t < stride) r[t] += r[t + stride];
        __syncthreads();
    }
    if (t == 0) out[OFF_Z] = 0.001f * (r[0] / (float)TOKENS);
}

extern "C" void kernel_launch(void* const* d_in, const int* in_sizes, int n_in,
                              void* d_out, int out_size) {
    const float* x = (const float*)d_in[0];
    const float* w = (const float*)d_in[1];
    float* out = (float*)d_out;

    cudaFuncSetAttribute(fused_kernel, cudaFuncAttributeMaxDynamicSharedMemorySize, SMEM_TOTAL);

    wsplit_kernel<<<64, 256>>>(w);
    fused_kernel<<<TOKENS / BM, NTH, SMEM_TOTAL>>>(x, out);
    zfin_kernel<<<1, TOKENS / BM>>>(out);
}

// round 14
// speedup vs baseline: 2.2142x; 1.0228x over previous
#include <cuda_runtime.h>
#include <cuda_bf16.h>
#include <cstdint>
#include <cstddef>

#define TOKENS 16384
#define HIDDEN 2048
#define NEXP   64
#define BM     128
#define BK     64
#define NIT    (HIDDEN / BK)   // 32
#define NTH    512

#define OFF_GATES (TOKENS * 2)
#define OFF_SEL   (OFF_GATES + TOKENS * NEXP)
#define OFF_Z     (OFF_SEL + TOKENS * 2)

// ---- smem layout (bytes, dynamic) ----
#define ASTRB 144
#define ALVL  (BM * ASTRB)          // 18432
#define ABUF  (3 * ALVL)            // 55296
#define BLVL  (NEXP * ASTRB)        // 9216
#define BBUF  (3 * BLVL)            // 27648
#define TILEB (ABUF + BBUF)         // 82944
#define SM_ZRED  0                  // 16 floats
#define SM_FLAG  64
#define SM_TILES 1024
#define SMEM_TOTAL (SM_TILES + 2 * TILEB)   // 166912
#define STRL 65

__device__ unsigned int g_wsplit[3 * 64 * 1024];
__device__ float g_zpart[TOKENS / BM];
__device__ unsigned int g_cnt;

// ---------------- helpers ----------------
__device__ __forceinline__ uint32_t smem_u32(const void* p) {
    uint32_t a;
    asm("{ .reg .u64 t; cvta.to.shared.u64 t, %1; cvt.u32.u64 %0, t; }" : "=r"(a) : "l"(p));
    return a;
}
__device__ __forceinline__ void ldsm4(uint32_t* r, uint32_t addr) {
    asm volatile("ldmatrix.sync.aligned.m8n8.x4.shared.b16 {%0,%1,%2,%3}, [%4];"
                 : "=r"(r[0]), "=r"(r[1]), "=r"(r[2]), "=r"(r[3]) : "r"(addr));
}
__device__ __forceinline__ void mma16816(float* d, const uint32_t* a, const uint32_t* b) {
    asm volatile("mma.sync.aligned.m16n8k16.row.col.f32.bf16.bf16.f32 "
                 "{%0,%1,%2,%3}, {%4,%5,%6,%7}, {%8,%9}, {%0,%1,%2,%3};"
                 : "+f"(d[0]), "+f"(d[1]), "+f"(d[2]), "+f"(d[3])
                 : "r"(a[0]), "r"(a[1]), "r"(a[2]), "r"(a[3]), "r"(b[0]), "r"(b[1]));
}
__device__ __forceinline__ void sts64(uint32_t a, uint32_t lo, uint32_t hi) {
    asm volatile("st.shared.v2.b32 [%0], {%1, %2};" :: "r"(a), "r"(lo), "r"(hi) : "memory");
}
__device__ __forceinline__ void cpasync16(uint32_t dst, const void* src) {
    asm volatile("cp.async.cg.shared.global [%0], [%1], 16;" :: "r"(dst), "l"(src) : "memory");
}
__device__ __forceinline__ void cpasync_commit() {
    asm volatile("cp.async.commit_group;" ::: "memory");
}
__device__ __forceinline__ void cpasync_wait0() {
    asm volatile("cp.async.wait_group 0;" ::: "memory");
}
// 3-way bf16 split of two floats (lo=x0, hi=x1); residuals exact (Sterbenz).
__device__ __forceinline__ void split2(float x0, float x1,
                                       uint32_t& p0, uint32_t& p1, uint32_t& p2) {
    asm("cvt.rn.satfinite.bf16x2.f32 %0, %1, %2;" : "=r"(p0) : "f"(x1), "f"(x0));
    float f0lo = __uint_as_float(p0 << 16);
    float f0hi = __uint_as_float(p0 & 0xffff0000u);
    float r0 = x0 - f0lo, r1 = x1 - f0hi;
    asm("cvt.rn.satfinite.bf16x2.f32 %0, %1, %2;" : "=r"(p1) : "f"(r1), "f"(r0));
    float f1lo = __uint_as_float(p1 << 16);
    float f1hi = __uint_as_float(p1 & 0xffff0000u);
    float s0 = r0 - f1lo, s1 = r1 - f1hi;
    asm("cvt.rn.satfinite.bf16x2.f32 %0, %1, %2;" : "=r"(p2) : "f"(s1), "f"(s0));
}
__device__ __forceinline__ void warp_argmax(float& v, int& i) {
#pragma unroll
    for (int m = 16; m; m >>= 1) {
        float ov = __shfl_xor_sync(0xffffffffu, v, m);
        int   oi = __shfl_xor_sync(0xffffffffu, i, m);
        if (ov > v || (ov == v && oi < i)) { v = ov; i = oi; }
    }
}
__device__ __forceinline__ float warp_sum(float s) {
#pragma unroll
    for (int m = 16; m; m >>= 1) s += __shfl_xor_sync(0xffffffffu, s, m);
    return s;
}

// ---------------------------------------------------------------------------
// Pre-kernel: split w into 3 bf16 levels
// ---------------------------------------------------------------------------
__global__ void wsplit_kernel(const float* __restrict__ w) {
    const int p4 = blockIdx.x * blockDim.x + threadIdx.x;
    const float4 v0 = *(const float4*)(w + (size_t)p4 * 8);
    const float4 v1 = *(const float4*)(w + (size_t)p4 * 8 + 4);
    const float xs[8] = {v0.x, v0.y, v0.z, v0.w, v1.x, v1.y, v1.z, v1.w};
#pragma unroll
    for (int j = 0; j < 4; j++) {
        uint32_t a, b, c;
        split2(xs[2 * j], xs[2 * j + 1], a, b, c);
        g_wsplit[0 * 65536 + p4 * 4 + j] = a;
        g_wsplit[1 * 65536 + p4 * 4 + j] = b;
        g_wsplit[2 * 65536 + p4 * 4 + j] = c;
    }
}

// 8 mma over the 2x2x2 acc block
#define MMA8(ACC, AF, BF)                                              \
    do {                                                               \
        mma16816((ACC)[0], (AF)[0], &(BF)[0][0]);                      \
        mma16816((ACC)[1], (AF)[0], &(BF)[0][2]);                      \
        mma16816((ACC)[2], (AF)[0], &(BF)[1][0]);                      \
        mma16816((ACC)[3], (AF)[0], &(BF)[1][2]);                      \
        mma16816((ACC)[4], (AF)[1], &(BF)[0][0]);                      \
        mma16816((ACC)[5], (AF)[1], &(BF)[0][2]);                      \
        mma16816((ACC)[6], (AF)[1], &(BF)[1][0]);                      \
        mma16816((ACC)[7], (AF)[1], &(BF)[1][2]);                      \
    } while (0)

// ---------------------------------------------------------------------------
// Fused kernel: bf16x6 emulated-fp32 GEMM via mma.sync, chunked RN accumulation.
// grid = 128 CTAs, 512 threads (16 warps).
// Warp w: rows [((w>>2)&3)*32, +32) x experts [((w>>1)&1)*32, +32), k-half w&1.
// ---------------------------------------------------------------------------
__global__ __launch_bounds__(NTH, 1) void fused_kernel(const float* __restrict__ x,
                                                       float* __restrict__ out) {
    extern __shared__ __align__(1024) char smem[];
    const uint32_t sb = smem_u32(smem);
    const int t    = threadIdx.x;
    const int wid  = t >> 5;
    const int lane = t & 31;
    const int m0   = blockIdx.x * BM;

    // fill roles: thread -> x row t>>2, 16-col chunk (t&3)*16
    const int xrow = t >> 2;
    const int xcb  = (t & 3) * 16;
    const float* xg = x + (size_t)(m0 + xrow) * HIDDEN + xcb;

    // mma tile bases
    const int m_base = ((wid >> 2) & 3) * 32;
    const int n_base = ((wid >> 1) & 1) * 32;
    const int kh     = wid & 1;
    const uint32_t a_off = (uint32_t)((m_base + (lane & 15)) * ASTRB + (lane >> 4) * 16);
    const uint32_t b_off = (uint32_t)((n_base + (lane >> 4) * 8 + (lane & 7)) * ASTRB +
                                      ((lane >> 3) & 1) * 16);

    float run[8][4];
#pragma unroll
    for (int q = 0; q < 8; q++)
#pragma unroll
        for (int c = 0; c < 4; c++) run[q][c] = 0.f;

    float4 xa[4];

    // prologue: x prefetch + w cp.async for iter 0 -> buf0
#pragma unroll
    for (int j = 0; j < 4; j++) xa[j] = *(const float4*)(xg + 4 * j);
    {
        const uint32_t bb = sb + SM_TILES + ABUF;
#pragma unroll
        for (int i = 0; i < 3; i++) {
            const int idx = i * 512 + t;
            const int lvl = idx >> 9, r = idx & 511, row = r >> 3, c16 = r & 7;
            cpasync16(bb + lvl * BLVL + (uint32_t)(row * ASTRB + c16 * 16),
                      g_wsplit + lvl * 65536 + row * 1024 + c16 * 4);
        }
        cpasync_commit();
    }

    for (int it = 0; it < NIT; it++) {
        const uint32_t tb = sb + SM_TILES + (it & 1) * TILEB;
        const uint32_t abase = tb;
        const uint32_t bbase = tb + ABUF;

        // ---- fill: convert+store x (3 levels) ----
#pragma unroll
        for (int j = 0; j < 4; j++) {
            uint32_t a0, a1, a2, b0, b1, b2;
            split2(xa[j].x, xa[j].y, a0, a1, a2);
            split2(xa[j].z, xa[j].w, b0, b1, b2);
            const uint32_t off = (uint32_t)(xrow * ASTRB + (xcb + 4 * j) * 2);
            sts64(abase + 0 * ALVL + off, a0, b0);
            sts64(abase + 1 * ALVL + off, a1, b1);
            sts64(abase + 2 * ALVL + off, a2, b2);
        }
        cpasync_wait0();          // w(it) landed
        __syncthreads();          // single barrier per iteration

        // ---- prefetch next iter: x regs + w cp.async into other buffer ----
        if (it + 1 < NIT) {
            const int kc = (it + 1) * BK;
#pragma unroll
            for (int j = 0; j < 4; j++) xa[j] = *(const float4*)(xg + kc + 4 * j);
            const uint32_t bbn = sb + SM_TILES + ((it + 1) & 1) * TILEB + ABUF;
#pragma unroll
            for (int i = 0; i < 3; i++) {
                const int idx = i * 512 + t;
                const int lvl = idx >> 9, r = idx & 511, row = r >> 3, c16 = r & 7;
                cpasync16(bbn + lvl * BLVL + (uint32_t)(row * ASTRB + c16 * 16),
                          g_wsplit + lvl * 65536 + row * 1024 + (kc >> 1) + c16 * 4);
            }
            cpasync_commit();
        }

        // ---- per-chunk mma accumulator ----
        float acc[8][4];
#pragma unroll
        for (int q = 0; q < 8; q++)
#pragma unroll
            for (int c = 0; c < 4; c++) acc[q][c] = 0.f;

        const uint32_t ap = abase + a_off;
        const uint32_t bp = bbase + b_off;
#pragma unroll
        for (int j = 0; j < 2; j++) {
            const uint32_t ko = (uint32_t)((kh * 2 + j) * 32);
            uint32_t b0[2][4], bt[2][4], af[2][4];
            // resident B level 0
            ldsm4(b0[0], bp + 0 * BLVL + ko);
            ldsm4(b0[1], bp + 0 * BLVL + 16 * ASTRB + ko);
            // A level 2: A2*B0
            ldsm4(af[0], ap + 2 * ALVL + ko);
            ldsm4(af[1], ap + 2 * ALVL + 16 * ASTRB + ko);
            MMA8(acc, af, b0);
            // B level 1 + A level 1: A1*B1, A1*B0
            ldsm4(bt[0], bp + 1 * BLVL + ko);
            ldsm4(bt[1], bp + 1 * BLVL + 16 * ASTRB + ko);
            ldsm4(af[0], ap + 1 * ALVL + ko);
            ldsm4(af[1], ap + 1 * ALVL + 16 * ASTRB + ko);
            MMA8(acc, af, bt);
            MMA8(acc, af, b0);
            // A level 0: A0*B1, A0*B2, A0*B0 (largest last)
            ldsm4(af[0], ap + 0 * ALVL + ko);
            ldsm4(af[1], ap + 0 * ALVL + 16 * ASTRB + ko);
            MMA8(acc, af, bt);
            ldsm4(bt[0], bp + 2 * BLVL + ko);
            ldsm4(bt[1], bp + 2 * BLVL + 16 * ASTRB + ko);
            MMA8(acc, af, bt);
            MMA8(acc, af, b0);
        }
        // fold chunk into RN fp32 running sums
#pragma unroll
        for (int q = 0; q < 8; q++)
#pragma unroll
            for (int c = 0; c < 4; c++) run[q][c] += acc[q][c];
    }

    __syncthreads();   // all ldsm reads done before aliasing tiles with Ls

    // ---- combine k-halves into Ls[128][65] ----
    float* Ls = (float*)(smem + SM_TILES);
    const int rr = lane >> 2;
    const int cc = (lane & 3) * 2;
    if (kh == 0) {
#pragma unroll
        for (int q = 0; q < 8; q++) {
            const int r0 = m_base + (q >> 2) * 16 + rr;
            const int c0 = n_base + (q & 3) * 8 + cc;
            Ls[r0 * STRL + c0]           = run[q][0];
            Ls[r0 * STRL + c0 + 1]       = run[q][1];
            Ls[(r0 + 8) * STRL + c0]     = run[q][2];
            Ls[(r0 + 8) * STRL + c0 + 1] = run[q][3];
        }
    }
    __syncthreads();
    if (kh == 1) {
#pragma unroll
        for (int q = 0; q < 8; q++) {
            const int r0 = m_base + (q >> 2) * 16 + rr;
            const int c0 = n_base + (q & 3) * 8 + cc;
            Ls[r0 * STRL + c0]           += run[q][0];
            Ls[r0 * STRL + c0 + 1]       += run[q][1];
            Ls[(r0 + 8) * STRL + c0]     += run[q][2];
            Ls[(r0 + 8) * STRL + c0 + 1] += run[q][3];
        }
    }
    __syncthreads();

    // ---- routing: warp per token, 8 tokens per warp ----
    const float NINF = __int_as_float(0xff800000);
    float zacc = 0.f;

    for (int st = 0; st < 8; st++) {
        const int tk = wid * 8 + st;
        const float* row = Ls + tk * STRL;
        const float v0 = row[lane];
        const float v1 = row[lane + 32];
        const int   i0 = lane, i1 = lane + 32;

        // pass 1
        float bv; int bi;
        if (v0 >= v1) { bv = v0; bi = i0; } else { bv = v1; bi = i1; }
        warp_argmax(bv, bi);
        const float mx1 = bv;
        const int   s1  = bi;

        const float ea0  = expf(v0 - mx1);
        const float ea1  = expf(v1 - mx1);
        const float sAll = warp_sum(ea0 + ea1);

        const float f0 = fmaxf(fabsf(v0), mx1);
        const float f1 = fmaxf(fabsf(v1), mx1);
        const bool mask10 = ((mx1 - v0) / f0) > 0.02f;
        const bool mask11 = ((mx1 - v1) / f1) > 0.02f;
        const float sum1  = warp_sum((mask10 ? 0.f : ea0) + (mask11 ? 0.f : ea1));
        const float mult1 = 1.0f / sum1;

        // pass 2
        const float w0 = (i0 == s1) ? NINF : v0;
        const float w1 = (i1 == s1) ? NINF : v1;
        float bv2; int bi2;
        if (w0 >= w1) { bv2 = w0; bi2 = i0; } else { bv2 = w1; bi2 = i1; }
        warp_argmax(bv2, bi2);
        const float mx2 = bv2;
        const int   s2  = bi2;

        const float g0 = fmaxf(fabsf(v0), mx2);
        const float g1 = fmaxf(fabsf(v1), mx2);
        const bool mask20 = ((mx2 - v0) / g0) > 0.02f;
        const bool mask21 = ((mx2 - v1) / g1) > 0.02f;
        const float e20 = (i0 == s1 || mask20) ? 0.f : expf(v0 - mx2);
        const float e21 = (i1 == s1 || mask21) ? 0.f : expf(v1 - mx2);
        const float sum2  = warp_sum(e20 + e21);
        const float mult2 = 1.0f / sum2;

        // outputs
        const int gtok = m0 + tk;
        const float invAll = 1.0f / sAll;
        out[OFF_GATES + (size_t)gtok * NEXP + lane]      = ea0 * invAll;
        out[OFF_GATES + (size_t)gtok * NEXP + lane + 32] = ea1 * invAll;
        if (lane == 0) {
            out[gtok * 2 + 0] = mult1;
            out[gtok * 2 + 1] = mult2;
            out[OFF_SEL + gtok * 2 + 0] = (float)s1;
            out[OFF_SEL + gtok * 2 + 1] = (float)s2;
            const float lse = mx1 + logf(sAll);
            zacc += lse * lse;
        }
    }

    // ---- z-loss: per-CTA partial, then last-CTA final reduction ----
    float* zred = (float*)(smem + SM_ZRED);
    if (lane == 0) zred[wid] = zacc;
    __syncthreads();
    if (t == 0) {
        float s = 0.f;
#pragma unroll
        for (int i = 0; i < 16; i++) s += zred[i];
        g_zpart[blockIdx.x] = s;
        __threadfence();
        const unsigned int tk = atomicAdd(&g_cnt, 1u);
        *(volatile int*)(smem + SM_FLAG) = (tk == (unsigned)(gridDim.x - 1)) ? 1 : 0;
    }
    __syncthreads();
    if (*(volatile int*)(smem + SM_FLAG) && wid == 0) {
        __threadfence();
        float s = 0.f;
#pragma unroll
        for (int i = 0; i < 4; i++) s += __ldcg(&g_zpart[lane * 4 + i]);
        s = warp_sum(s);
        if (lane == 0) {
            out[OFF_Z] = 0.001f * (s / (float)TOKENS);
            g_cnt = 0u;
        }
    }
}

extern "C" void kernel_launch(void* const* d_in, const int* in_sizes, int n_in,
                              void* d_out, int out_size) {
    const float* x = (const float*)d_in[0];
    const float* w = (const float*)d_in[1];
    float* out = (float*)d_out;

    cudaFuncSetAttribute(fused_kernel, cudaFuncAttributeMaxDynamicSharedMemorySize, SMEM_TOTAL);

    wsplit_kernel<<<64, 256>>>(w);
    fused_kernel<<<TOKENS / BM, NTH, SMEM_TOTAL>>>(x, out);
}